// round 1
// baseline (speedup 1.0000x reference)
#include <cuda_runtime.h>
#include <math.h>

// Problem constants
#define BB 64
#define TT 1380
#define XD 96
#define HD 192
#define CN 345

// Scratch (static __device__ arrays are the sanctioned scratch mechanism)
static __device__ float g_M1[(size_t)BB * CN * XD];   // W2 @ X[b]      : [B,345,96]
static __device__ float g_G [(size_t)BB * CN * HD];   // (M1 @ W1)*SCALE: [B,345,192]
static __device__ float g_S [(size_t)BB * CN * TT];   // logits         : [B,345,1380]
static __device__ float g_rmax[BB * CN];
static __device__ float g_rinv[BB * CN];

// ---------------------------------------------------------------------------
// Generic fp32 tiled GEMM: C[b] = alpha * A[b] @ op(B[b])
//   MODE 0: B row-major [K,N]        (NN)
//   MODE 1: B row-major [N,K] (NT — computes A @ B^T)
//   MODE 2: NN, but A entries are transformed on load:
//           a = exp(a - rowmax[gm]) * rinv[gm]   (softmax-on-the-fly)
// Tiles: 128x128x16, 256 threads, 8x8 per-thread microtile.
// ---------------------------------------------------------------------------
constexpr int BM = 128, BN = 128, BK = 16;

template <int MODE>
__global__ void __launch_bounds__(256, 2) gemm_tiled(
    const float* __restrict__ A, const float* __restrict__ B,
    float* __restrict__ C,
    int M, int N, int K,
    long sA, long sB, long sC, float alpha,
    const float* __restrict__ rmaxArr, const float* __restrict__ rinvArr,
    int statStride)
{
    const int b = blockIdx.z;
    A += (long)b * sA;
    B += (long)b * sB;
    C += (long)b * sC;
    const float* rmax = rmaxArr + (long)b * statStride;
    const float* rinv = rinvArr + (long)b * statStride;

    const int blockRow = blockIdx.y * BM;
    const int blockCol = blockIdx.x * BN;
    const int tid = threadIdx.x;
    const int tx = tid & 15;   // N direction (16)
    const int ty = tid >> 4;   // M direction (16)

    __shared__ float As[BK][BM + 4];
    __shared__ float Bs[BK][BN + 4];

    float acc[8][8];
#pragma unroll
    for (int i = 0; i < 8; i++)
#pragma unroll
        for (int j = 0; j < 8; j++) acc[i][j] = 0.0f;

    const int numK = (K + BK - 1) / BK;
    for (int kt = 0; kt < numK; kt++) {
        const int k0 = kt * BK;

        // ---- load A tile [BM x BK], store transposed As[k][m] ----
#pragma unroll
        for (int f = tid; f < (BM * BK) / 4; f += 256) {
            const int row = f >> 2;
            const int cg  = f & 3;
            const int gm = blockRow + row;
            const int gk = k0 + cg * 4;
            float4 v = make_float4(0.f, 0.f, 0.f, 0.f);
            if (gm < M && gk < K) {
                v = *reinterpret_cast<const float4*>(A + (long)gm * K + gk);
                if (MODE == 2) {
                    const float mx = rmax[gm];
                    const float rv = rinv[gm];
                    v.x = __expf(v.x - mx) * rv;
                    v.y = __expf(v.y - mx) * rv;
                    v.z = __expf(v.z - mx) * rv;
                    v.w = __expf(v.w - mx) * rv;
                }
            }
            As[cg * 4 + 0][row] = v.x;
            As[cg * 4 + 1][row] = v.y;
            As[cg * 4 + 2][row] = v.z;
            As[cg * 4 + 3][row] = v.w;
        }

        // ---- load B tile into Bs[k][n] ----
        if (MODE == 1) {
            // B row-major [N,K]; tile rows are n, 4 float4 over k each
#pragma unroll
            for (int f = tid; f < (BN * BK) / 4; f += 256) {
                const int row = f >> 2;
                const int cg  = f & 3;
                const int gn = blockCol + row;
                const int gk = k0 + cg * 4;
                float4 v = make_float4(0.f, 0.f, 0.f, 0.f);
                if (gn < N && gk < K)
                    v = *reinterpret_cast<const float4*>(B + (long)gn * K + gk);
                Bs[cg * 4 + 0][row] = v.x;
                Bs[cg * 4 + 1][row] = v.y;
                Bs[cg * 4 + 2][row] = v.z;
                Bs[cg * 4 + 3][row] = v.w;
            }
        } else {
            // B row-major [K,N]
#pragma unroll
            for (int f = tid; f < (BK * BN) / 4; f += 256) {
                const int r  = f >> 5;         // k within tile (BN/4 = 32)
                const int cg = f & 31;
                const int gk = k0 + r;
                const int gn = blockCol + cg * 4;
                float4 v = make_float4(0.f, 0.f, 0.f, 0.f);
                if (gk < K && gn < N)
                    v = *reinterpret_cast<const float4*>(B + (long)gk * N + gn);
                *reinterpret_cast<float4*>(&Bs[r][cg * 4]) = v;
            }
        }

        __syncthreads();

        // ---- microkernel ----
#pragma unroll
        for (int kk = 0; kk < BK; kk++) {
            float ar[8], br[8];
            float4 a0 = *reinterpret_cast<const float4*>(&As[kk][ty * 8]);
            float4 a1 = *reinterpret_cast<const float4*>(&As[kk][ty * 8 + 4]);
            float4 b0 = *reinterpret_cast<const float4*>(&Bs[kk][tx * 8]);
            float4 b1 = *reinterpret_cast<const float4*>(&Bs[kk][tx * 8 + 4]);
            ar[0] = a0.x; ar[1] = a0.y; ar[2] = a0.z; ar[3] = a0.w;
            ar[4] = a1.x; ar[5] = a1.y; ar[6] = a1.z; ar[7] = a1.w;
            br[0] = b0.x; br[1] = b0.y; br[2] = b0.z; br[3] = b0.w;
            br[4] = b1.x; br[5] = b1.y; br[6] = b1.z; br[7] = b1.w;
#pragma unroll
            for (int i = 0; i < 8; i++)
#pragma unroll
                for (int j = 0; j < 8; j++)
                    acc[i][j] = fmaf(ar[i], br[j], acc[i][j]);
        }

        __syncthreads();
    }

    // ---- epilogue ----
#pragma unroll
    for (int i = 0; i < 8; i++) {
        const int gm = blockRow + ty * 8 + i;
        if (gm >= M) continue;
#pragma unroll
        for (int jg = 0; jg < 2; jg++) {
            const int gn = blockCol + tx * 8 + jg * 4;
            if (gn < N) {
                float4 v;
                v.x = acc[i][jg * 4 + 0] * alpha;
                v.y = acc[i][jg * 4 + 1] * alpha;
                v.z = acc[i][jg * 4 + 2] * alpha;
                v.w = acc[i][jg * 4 + 3] * alpha;
                *reinterpret_cast<float4*>(C + (long)gm * N + gn) = v;
            }
        }
    }
}

// ---------------------------------------------------------------------------
// Per-row softmax statistics over the logits: rowmax and 1/sum(exp(x - max))
// One block per row (B*CN rows of length TT).
// ---------------------------------------------------------------------------
__global__ void __launch_bounds__(256) softmax_stats(
    const float* __restrict__ S, float* __restrict__ rmax,
    float* __restrict__ rinv, int N)
{
    const long row = blockIdx.x;
    const float* p = S + row * (long)N;
    const int tid = threadIdx.x;
    __shared__ float sh[256];

    float mx = -3.402823e38f;
    for (int i = tid; i < N; i += 256) mx = fmaxf(mx, p[i]);
    sh[tid] = mx;
    __syncthreads();
    for (int s = 128; s > 0; s >>= 1) {
        if (tid < s) sh[tid] = fmaxf(sh[tid], sh[tid + s]);
        __syncthreads();
    }
    mx = sh[0];
    __syncthreads();

    float sum = 0.f;
    for (int i = tid; i < N; i += 256) sum += __expf(p[i] - mx);
    sh[tid] = sum;
    __syncthreads();
    for (int s = 128; s > 0; s >>= 1) {
        if (tid < s) sh[tid] += sh[tid + s];
        __syncthreads();
    }
    if (tid == 0) {
        rmax[row] = mx;
        rinv[row] = 1.0f / sh[0];
    }
}

// ---------------------------------------------------------------------------
// Launch:  C = softmax( ((W2 @ X) @ W1 * SCALE) @ H^T ) @ H    per batch
// ---------------------------------------------------------------------------
extern "C" void kernel_launch(void* const* d_in, const int* in_sizes, int n_in,
                              void* d_out, int out_size)
{
    const float* X  = (const float*)d_in[0];   // [B,T,XD]
    const float* H  = (const float*)d_in[1];   // [B,T,HD]
    const float* W1 = (const float*)d_in[2];   // [XD,HD]
    const float* W2 = (const float*)d_in[3];   // [CN,T]
    float* out = (float*)d_out;                // [B,CN,HD]

    float *M1, *G, *S, *rmax, *rinv;
    cudaGetSymbolAddress((void**)&M1,   g_M1);
    cudaGetSymbolAddress((void**)&G,    g_G);
    cudaGetSymbolAddress((void**)&S,    g_S);
    cudaGetSymbolAddress((void**)&rmax, g_rmax);
    cudaGetSymbolAddress((void**)&rinv, g_rinv);

    const float SCALE = (float)(1.0 / (sqrt((double)XD) * sqrt((double)HD)));

    // K1: M1[b] = W2 @ X[b]        [CN,XD], K=T
    gemm_tiled<0><<<dim3(1, 3, BB), 256>>>(
        W2, X, M1, CN, XD, TT,
        0L, (long)TT * XD, (long)CN * XD, 1.0f, rmax, rinv, 0);

    // K2: G[b] = (M1[b] @ W1) * SCALE   [CN,HD], K=XD
    gemm_tiled<0><<<dim3(2, 3, BB), 256>>>(
        M1, W1, G, CN, HD, XD,
        (long)CN * XD, 0L, (long)CN * HD, SCALE, rmax, rinv, 0);

    // K3: S[b] = G[b] @ H[b]^T     [CN,T], K=HD
    gemm_tiled<1><<<dim3(11, 3, BB), 256>>>(
        G, H, S, CN, TT, HD,
        (long)CN * HD, (long)TT * HD, (long)CN * TT, 1.0f, rmax, rinv, 0);

    // K4: per-row softmax stats over S
    softmax_stats<<<BB * CN, 256>>>(S, rmax, rinv, TT);

    // K5: out[b] = softmax(S[b]) @ H[b]   [CN,HD], K=T
    gemm_tiled<2><<<dim3(2, 3, BB), 256>>>(
        S, H, out, CN, HD, TT,
        (long)CN * TT, (long)TT * HD, (long)CN * HD, 1.0f, rmax, rinv, CN);
}